// round 1
// baseline (speedup 1.0000x reference)
#include <cuda_runtime.h>

// ---------------------------------------------------------------------------
// Forecaster_PONI: encoder (3x strided conv) + 10-step ConvGRU decoder stack.
// Round 1: correct fp32 direct convolutions, smem-tiled, register-blocked
// (2x2 pixels x 8 cout per thread). All scratch in __device__ globals.
// ---------------------------------------------------------------------------

__device__ __forceinline__ float lrelu_f(float v) { return v > 0.f ? v : 0.2f * v; }

// ------------------------------ scratch buffers ----------------------------
// frame order for e-buffers: f = t*16 + b  (dense per step)
__device__ float g_e1[160 * 16 * 96 * 96];
__device__ float g_e2[160 * 64 * 48 * 48];
__device__ float g_e3[160 * 96 * 24 * 24];
__device__ float g_c3[2][16 * 96 * 24 * 24];
__device__ float g_c2[2][16 * 64 * 48 * 48];
__device__ float g_c1[2][16 * 16 * 96 * 96];
__device__ float g_g3[16 * 192 * 24 * 24];
__device__ float g_g2[16 * 128 * 48 * 48];
__device__ float g_g1[16 * 32 * 96 * 96];
__device__ float g_o3[16 * 64 * 48 * 48];
__device__ float g_o2[16 * 16 * 96 * 96];
__device__ float g_o1[16 * 8 * 192 * 192];

// ---------------------------------------------------------------------------
// Generic 3x3 stride-1 SAME conv over [x1 (C1 ch) ++ x2 (C2 ch)].
// ACT: 0 none, 1 lrelu, 2 sigmoid
// MODE: 1 = plain concat conv (gate conv). gates unused.
//       2 = GRU candidate: x2 contribution scaled by r = gates[n][C2+c2],
//           epilogue: out = (1-z)*h + z*act(acc+b), z = gates[n][co], h = x2.
// Each thread: 2x2 output pixels x COT output channels.
// ---------------------------------------------------------------------------
template<int C1, int C2, int CO, int H, int W, int ACT, int MODE,
         int TY, int TX, int CICH, int COT>
__global__ void __launch_bounds__((TY / 2) * (TX / 2))
conv3x3_k(const float* __restrict__ x1, const float* __restrict__ x2,
          const float* __restrict__ gates, const float* __restrict__ wgt,
          const float* __restrict__ bias, float* __restrict__ out)
{
    constexpr int CI = C1 + C2;
    constexpr int SH = TY + 2, SW = TX + 2;
    constexpr int NT = (TY / 2) * (TX / 2);
    constexpr int TILES_X = (W + TX - 1) / TX;
    __shared__ float s_in[CICH][SH][SW];
    __shared__ float s_w[CICH][COT][9];

    const int n   = blockIdx.z;
    const int cob = blockIdx.y * COT;
    const int ty0 = (blockIdx.x / TILES_X) * TY;
    const int tx0 = (blockIdx.x % TILES_X) * TX;
    const int tid = threadIdx.x;
    const int lx  = tid % (TX / 2);
    const int ly  = tid / (TX / 2);

    float acc[COT][2][2];
#pragma unroll
    for (int c = 0; c < COT; c++) {
        acc[c][0][0] = acc[c][0][1] = acc[c][1][0] = acc[c][1][1] = 0.f;
    }

    for (int ci0 = 0; ci0 < CI; ci0 += CICH) {
        for (int idx = tid; idx < CICH * SH * SW; idx += NT) {
            int c   = idx / (SH * SW);
            int rem = idx - c * (SH * SW);
            int iy  = rem / SW;
            int ix  = rem - iy * SW;
            int gy = ty0 + iy - 1, gx = tx0 + ix - 1;
            int ci = ci0 + c;
            float v = 0.f;
            if ((unsigned)gy < (unsigned)H && (unsigned)gx < (unsigned)W) {
                if (ci < C1) {
                    v = x1[((n * C1 + ci) * H + gy) * W + gx];
                } else {
                    int c2 = ci - C1;
                    v = x2[((n * C2 + c2) * H + gy) * W + gx];
                    if (MODE == 2)
                        v *= gates[((n * 2 * C2 + C2 + c2) * H + gy) * W + gx];
                }
            }
            s_in[c][iy][ix] = v;
        }
        for (int idx = tid; idx < CICH * COT * 9; idx += NT) {
            int c   = idx / (COT * 9);
            int rem = idx - c * (COT * 9);
            int co  = rem / 9;
            int k   = rem - co * 9;
            s_w[c][co][k] = wgt[((cob + co) * CI + (ci0 + c)) * 9 + k];
        }
        __syncthreads();

        for (int c = 0; c < CICH; c++) {
            float p[4][4];
#pragma unroll
            for (int i = 0; i < 4; i++)
#pragma unroll
                for (int j = 0; j < 4; j++)
                    p[i][j] = s_in[c][2 * ly + i][2 * lx + j];
#pragma unroll
            for (int co = 0; co < COT; co++) {
#pragma unroll
                for (int ky = 0; ky < 3; ky++)
#pragma unroll
                    for (int kx = 0; kx < 3; kx++) {
                        float wv = s_w[c][co][ky * 3 + kx];
                        acc[co][0][0] = fmaf(p[ky][kx],         wv, acc[co][0][0]);
                        acc[co][0][1] = fmaf(p[ky][kx + 1],     wv, acc[co][0][1]);
                        acc[co][1][0] = fmaf(p[ky + 1][kx],     wv, acc[co][1][0]);
                        acc[co][1][1] = fmaf(p[ky + 1][kx + 1], wv, acc[co][1][1]);
                    }
            }
        }
        __syncthreads();
    }

    const int oy = ty0 + 2 * ly, ox = tx0 + 2 * lx;
#pragma unroll
    for (int co = 0; co < COT; co++) {
        float bv = bias[cob + co];
#pragma unroll
        for (int i = 0; i < 2; i++)
#pragma unroll
            for (int j = 0; j < 2; j++) {
                int y = oy + i, x = ox + j;
                if (y < H && x < W) {
                    float v = acc[co][i][j] + bv;
                    if (ACT == 1) v = lrelu_f(v);
                    if (ACT == 2) v = 1.f / (1.f + __expf(-v));
                    int off = ((n * CO + cob + co) * H + y) * W + x;
                    if (MODE == 2) {
                        float z = gates[((n * 2 * CO + cob + co) * H + y) * W + x];
                        float h = x2[off];   // C2 == CO in candidate mode
                        v = (1.f - z) * h + z * v;
                    }
                    out[off] = v;
                }
            }
    }
}

// ---------------------------------------------------------------------------
// 3x3 stride-2 SAME conv (encoder). pad_lo = 0: out[y] uses in[2y + ky].
// REMAP (enc1 only, CI==1): frame n -> source frame (n%16)*10 + n/16
// (folds the [B,T]->[T,B] transpose into the read).
// One output pixel + COT channels per thread.
// ---------------------------------------------------------------------------
template<int CI, int CO, int HIN, bool REMAP, int TY, int TX, int CICH, int COT>
__global__ void __launch_bounds__(TY * TX)
conv3x3s2_k(const float* __restrict__ x, const float* __restrict__ wgt,
            const float* __restrict__ bias, float* __restrict__ out)
{
    constexpr int WIN = HIN, HO = HIN / 2, WO = HIN / 2;
    constexpr int SH = 2 * TY + 1, SW = 2 * TX + 1;
    constexpr int NT = TY * TX;
    constexpr int TILES_X = (WO + TX - 1) / TX;
    __shared__ float s_in[CICH][SH][SW];
    __shared__ float s_w[CICH][COT][9];

    const int n   = blockIdx.z;
    const int cob = blockIdx.y * COT;
    const int ty0 = (blockIdx.x / TILES_X) * TY;
    const int tx0 = (blockIdx.x % TILES_X) * TX;
    const int tid = threadIdx.x;
    const int lx  = tid % TX;
    const int ly  = tid / TX;

    float acc[COT];
#pragma unroll
    for (int c = 0; c < COT; c++) acc[c] = 0.f;

    for (int ci0 = 0; ci0 < CI; ci0 += CICH) {
        for (int idx = tid; idx < CICH * SH * SW; idx += NT) {
            int c   = idx / (SH * SW);
            int rem = idx - c * (SH * SW);
            int iy  = rem / SW;
            int ix  = rem - iy * SW;
            int gy = 2 * ty0 + iy, gx = 2 * tx0 + ix;
            int ci = ci0 + c;
            float v = 0.f;
            if (gy < HIN && gx < WIN) {
                int frame = REMAP ? ((n % 16) * 10 + n / 16) : n;
                v = x[((frame * CI + ci) * HIN + gy) * WIN + gx];
            }
            s_in[c][iy][ix] = v;
        }
        for (int idx = tid; idx < CICH * COT * 9; idx += NT) {
            int c   = idx / (COT * 9);
            int rem = idx - c * (COT * 9);
            int co  = rem / 9;
            int k   = rem - co * 9;
            s_w[c][co][k] = wgt[((cob + co) * CI + (ci0 + c)) * 9 + k];
        }
        __syncthreads();

        for (int c = 0; c < CICH; c++) {
            float p[3][3];
#pragma unroll
            for (int r = 0; r < 3; r++)
#pragma unroll
                for (int cc = 0; cc < 3; cc++)
                    p[r][cc] = s_in[c][2 * ly + r][2 * lx + cc];
#pragma unroll
            for (int co = 0; co < COT; co++) {
#pragma unroll
                for (int k = 0; k < 9; k++)
                    acc[co] = fmaf(p[k / 3][k % 3], s_w[c][co][k], acc[co]);
            }
        }
        __syncthreads();
    }

    const int oy = ty0 + ly, ox = tx0 + lx;
    if (oy < HO && ox < WO) {
#pragma unroll
        for (int co = 0; co < COT; co++) {
            float v = lrelu_f(acc[co] + bias[cob + co]);
            out[((n * CO + cob + co) * HO + oy) * WO + ox] = v;
        }
    }
}

// ---------------------------------------------------------------------------
// 4x4 stride-2 SAME transposed conv (lax.conv_transpose, kernel NOT flipped):
// out[2i+dy][2j+dx] = sum_{a,b in {0,1}} in[i-1+a+dy][j-1+b+dx]
//                                        * w[co][ci][dy+2a][dx+2b]
// Thread owns input pixel (i,j) -> 2x2 outputs, COT channels. lrelu epilogue.
// ---------------------------------------------------------------------------
template<int CI, int CO, int HIN, int TY, int TX, int CICH, int COT>
__global__ void __launch_bounds__(TY * TX)
deconv4x4_k(const float* __restrict__ x, const float* __restrict__ wgt,
            const float* __restrict__ bias, float* __restrict__ out)
{
    constexpr int WIN = HIN, HO = 2 * HIN, WO = 2 * HIN;
    constexpr int SH = TY + 2, SW = TX + 2;
    constexpr int NT = TY * TX;
    constexpr int TILES_X = (WIN + TX - 1) / TX;
    __shared__ float s_in[CICH][SH][SW];
    __shared__ float s_w[CICH][COT][16];

    const int n   = blockIdx.z;
    const int cob = blockIdx.y * COT;
    const int ty0 = (blockIdx.x / TILES_X) * TY;
    const int tx0 = (blockIdx.x % TILES_X) * TX;
    const int tid = threadIdx.x;
    const int lx  = tid % TX;
    const int ly  = tid / TX;

    float acc[COT][2][2];
#pragma unroll
    for (int c = 0; c < COT; c++) {
        acc[c][0][0] = acc[c][0][1] = acc[c][1][0] = acc[c][1][1] = 0.f;
    }

    for (int ci0 = 0; ci0 < CI; ci0 += CICH) {
        for (int idx = tid; idx < CICH * SH * SW; idx += NT) {
            int c   = idx / (SH * SW);
            int rem = idx - c * (SH * SW);
            int iy  = rem / SW;
            int ix  = rem - iy * SW;
            int gy = ty0 + iy - 1, gx = tx0 + ix - 1;
            float v = 0.f;
            if ((unsigned)gy < (unsigned)HIN && (unsigned)gx < (unsigned)WIN)
                v = x[((n * CI + (ci0 + c)) * HIN + gy) * WIN + gx];
            s_in[c][iy][ix] = v;
        }
        for (int idx = tid; idx < CICH * COT * 16; idx += NT) {
            int c   = idx / (COT * 16);
            int rem = idx - c * (COT * 16);
            int co  = rem / 16;
            int k   = rem - co * 16;
            s_w[c][co][k] = wgt[((cob + co) * CI + (ci0 + c)) * 16 + k];
        }
        __syncthreads();

        for (int c = 0; c < CICH; c++) {
            float p[3][3];
#pragma unroll
            for (int r = 0; r < 3; r++)
#pragma unroll
                for (int cc = 0; cc < 3; cc++)
                    p[r][cc] = s_in[c][ly + r][lx + cc];
#pragma unroll
            for (int co = 0; co < COT; co++) {
#pragma unroll
                for (int dy = 0; dy < 2; dy++)
#pragma unroll
                    for (int dx = 0; dx < 2; dx++)
#pragma unroll
                        for (int a = 0; a < 2; a++)
#pragma unroll
                            for (int b = 0; b < 2; b++)
                                acc[co][dy][dx] =
                                    fmaf(p[a + dy][b + dx],
                                         s_w[c][co][(dy + 2 * a) * 4 + (dx + 2 * b)],
                                         acc[co][dy][dx]);
            }
        }
        __syncthreads();
    }

    const int iy = ty0 + ly, ix = tx0 + lx;
    if (iy < HIN && ix < WIN) {
#pragma unroll
        for (int co = 0; co < COT; co++) {
            float bv = bias[cob + co];
#pragma unroll
            for (int dy = 0; dy < 2; dy++)
#pragma unroll
                for (int dx = 0; dx < 2; dx++) {
                    float v = lrelu_f(acc[co][dy][dx] + bv);
                    out[((n * CO + cob + co) * HO + 2 * iy + dy) * WO + 2 * ix + dx] = v;
                }
        }
    }
}

// ---------------------------------------------------------------------------
// Head: 3x3 conv, 8 -> 1 channels, 192x192, no activation.
// ---------------------------------------------------------------------------
__global__ void head_k(const float* __restrict__ x, const float* __restrict__ w,
                       const float* __restrict__ b, float* __restrict__ out)
{
    __shared__ float sw[72];
    __shared__ float sb;
    if (threadIdx.x < 72) sw[threadIdx.x] = w[threadIdx.x];
    if (threadIdx.x == 0) sb = b[0];
    __syncthreads();

    const int HW = 192 * 192;
    int idx = blockIdx.x * blockDim.x + threadIdx.x;
    if (idx >= 16 * HW) return;
    int n   = idx / HW;
    int rem = idx - n * HW;
    int y   = rem / 192;
    int xq  = rem - y * 192;

    float acc = sb;
#pragma unroll
    for (int ci = 0; ci < 8; ci++) {
        const float* xp = x + (n * 8 + ci) * HW;
#pragma unroll
        for (int ky = 0; ky < 3; ky++) {
            int yy = y + ky - 1;
            if ((unsigned)yy >= 192u) continue;
#pragma unroll
            for (int kx = 0; kx < 3; kx++) {
                int xx = xq + kx - 1;
                if ((unsigned)xx >= 192u) continue;
                acc = fmaf(xp[yy * 192 + xx], sw[ci * 9 + ky * 3 + kx], acc);
            }
        }
    }
    out[idx] = acc;
}

// ---------------------------------------------------------------------------
// host
// ---------------------------------------------------------------------------
extern "C" void kernel_launch(void* const* d_in, const int* in_sizes, int n_in,
                              void* d_out, int out_size)
{
    const float* h1     = (const float*)d_in[0];
    const float* h2     = (const float*)d_in[1];
    const float* h3     = (const float*)d_in[2];
    const float* y_add  = (const float*)d_in[3];
    const float* enc_w1 = (const float*)d_in[4];
    const float* enc_b1 = (const float*)d_in[5];
    const float* enc_w2 = (const float*)d_in[6];
    const float* enc_b2 = (const float*)d_in[7];
    const float* enc_w3 = (const float*)d_in[8];
    const float* enc_b3 = (const float*)d_in[9];
    const float* g3wg   = (const float*)d_in[10];
    const float* g3bg   = (const float*)d_in[11];
    const float* g3wc   = (const float*)d_in[12];
    const float* g3bc   = (const float*)d_in[13];
    const float* g2wg   = (const float*)d_in[14];
    const float* g2bg   = (const float*)d_in[15];
    const float* g2wc   = (const float*)d_in[16];
    const float* g2bc   = (const float*)d_in[17];
    const float* g1wg   = (const float*)d_in[18];
    const float* g1bg   = (const float*)d_in[19];
    const float* g1wc   = (const float*)d_in[20];
    const float* g1bc   = (const float*)d_in[21];
    const float* s3w    = (const float*)d_in[22];
    const float* s3b    = (const float*)d_in[23];
    const float* s2w    = (const float*)d_in[24];
    const float* s2b    = (const float*)d_in[25];
    const float* s1w    = (const float*)d_in[26];
    const float* s1b    = (const float*)d_in[27];
    const float* hw     = (const float*)d_in[28];
    const float* hb     = (const float*)d_in[29];
    float* out = (float*)d_out;

    float *e1, *e2, *e3, *c3b, *c2b, *c1b, *gg3, *gg2, *gg1, *o3, *o2, *o1;
    cudaGetSymbolAddress((void**)&e1, g_e1);
    cudaGetSymbolAddress((void**)&e2, g_e2);
    cudaGetSymbolAddress((void**)&e3, g_e3);
    cudaGetSymbolAddress((void**)&c3b, g_c3);
    cudaGetSymbolAddress((void**)&c2b, g_c2);
    cudaGetSymbolAddress((void**)&c1b, g_c1);
    cudaGetSymbolAddress((void**)&gg3, g_g3);
    cudaGetSymbolAddress((void**)&gg2, g_g2);
    cudaGetSymbolAddress((void**)&gg1, g_g1);
    cudaGetSymbolAddress((void**)&o3, g_o3);
    cudaGetSymbolAddress((void**)&o2, g_o2);
    cudaGetSymbolAddress((void**)&o1, g_o1);

    const size_t SZ3 = (size_t)16 * 96 * 24 * 24;
    const size_t SZ2 = (size_t)16 * 64 * 48 * 48;
    const size_t SZ1 = (size_t)16 * 16 * 96 * 96;

    // -------- encoder over all 160 frames (transpose folded into enc1) -----
    conv3x3s2_k<1, 16, 192, true, 16, 16, 1, 16><<<dim3(36, 1, 160), 256>>>(
        y_add, enc_w1, enc_b1, e1);
    conv3x3s2_k<16, 64, 96, false, 16, 16, 8, 8><<<dim3(9, 8, 160), 256>>>(
        e1, enc_w2, enc_b2, e2);
    conv3x3s2_k<64, 96, 48, false, 16, 16, 8, 8><<<dim3(4, 12, 160), 256>>>(
        e2, enc_w3, enc_b3, e3);

    // -------- init GRU states (ping buffers = index 0) ----------------------
    cudaMemcpyAsync(c3b, h3, SZ3 * sizeof(float), cudaMemcpyDeviceToDevice);
    cudaMemcpyAsync(c2b, h2, SZ2 * sizeof(float), cudaMemcpyDeviceToDevice);
    cudaMemcpyAsync(c1b, h1, SZ1 * sizeof(float), cudaMemcpyDeviceToDevice);

    for (int t = 0; t < 10; t++) {
        const float* x3 = e3 + (size_t)t * 16 * 96 * 24 * 24;
        float* c3c = c3b + (size_t)(t & 1) * SZ3;
        float* c3n = c3b + (size_t)((t + 1) & 1) * SZ3;
        float* c2c = c2b + (size_t)(t & 1) * SZ2;
        float* c2n = c2b + (size_t)((t + 1) & 1) * SZ2;
        float* c1c = c1b + (size_t)(t & 1) * SZ1;
        float* c1n = c1b + (size_t)((t + 1) & 1) * SZ1;

        // --- level 3 (24x24, 96 ch) ---
        conv3x3_k<96, 96, 192, 24, 24, 2, 1, 24, 24, 8, 8>
            <<<dim3(1, 24, 16), 144>>>(x3, c3c, nullptr, g3wg, g3bg, gg3);
        conv3x3_k<96, 96, 96, 24, 24, 1, 2, 24, 24, 8, 8>
            <<<dim3(1, 12, 16), 144>>>(x3, c3c, gg3, g3wc, g3bc, c3n);
        deconv4x4_k<96, 64, 24, 24, 24, 8, 8>
            <<<dim3(1, 8, 16), 576>>>(c3n, s3w, s3b, o3);

        // --- level 2 (48x48, 64 ch) ---
        conv3x3_k<64, 64, 128, 48, 48, 2, 1, 16, 48, 8, 8>
            <<<dim3(3, 16, 16), 192>>>(o3, c2c, nullptr, g2wg, g2bg, gg2);
        conv3x3_k<64, 64, 64, 48, 48, 1, 2, 16, 48, 8, 8>
            <<<dim3(3, 8, 16), 192>>>(o3, c2c, gg2, g2wc, g2bc, c2n);
        deconv4x4_k<64, 16, 48, 16, 48, 8, 4>
            <<<dim3(3, 4, 16), 768>>>(c2n, s2w, s2b, o2);

        // --- level 1 (96x96, 16 ch) ---
        conv3x3_k<16, 16, 32, 96, 96, 2, 1, 16, 48, 8, 8>
            <<<dim3(12, 4, 16), 192>>>(o2, c1c, nullptr, g1wg, g1bg, gg1);
        conv3x3_k<16, 16, 16, 96, 96, 1, 2, 16, 48, 8, 8>
            <<<dim3(12, 2, 16), 192>>>(o2, c1c, gg1, g1wc, g1bc, c1n);
        deconv4x4_k<16, 8, 96, 16, 48, 8, 8>
            <<<dim3(12, 1, 16), 768>>>(c1n, s1w, s1b, o1);

        // --- head -> output slice [t] ---
        head_k<<<dim3((16 * 192 * 192 + 255) / 256), 256>>>(
            o1, hw, hb, out + (size_t)t * 16 * 192 * 192);
    }
}